// round 4
// baseline (speedup 1.0000x reference)
#include <cuda_runtime.h>
#include <math.h>

#define B_N   4096
#define M_N   8192
#define EMB   64
#define TAU   0.3f
#define NTHR  256
#define FINF  3.0e38f

__device__ __forceinline__ float gelu_exact(float x) {
    return 0.5f * x * (1.0f + erff(x * 0.70710678118654752440f));
}

// ---- top-4 slots with (distance, x, y) payload ----
__device__ __forceinline__ void takemin3(float& d, float& x, float& y,
                                         float ed, float ex, float ey) {
    if (ed < d) { d = ed; x = ex; y = ey; }
}
__device__ __forceinline__ void cmpswap3(float& da, float& xa, float& ya,
                                         float& db, float& xb, float& yb) {
    if (db < da) {
        float t;
        t = da; da = db; db = t;
        t = xa; xa = xb; xb = t;
        t = ya; ya = yb; yb = t;
    }
}

// insert (v, xx, yy) into sorted ascending 4-list d0<=d1<=d2v<=d3
#define INSERT3(v, xx, yy)                                                   \
    if ((v) < d3) {                                                          \
        if ((v) < d2v) {                                                     \
            d3 = d2v; x3 = x2; y3 = y2;                                      \
            if ((v) < d1) {                                                  \
                d2v = d1; x2 = x1; y2 = y1;                                  \
                if ((v) < d0) {                                              \
                    d1 = d0; x1 = x0; y1 = y0;                               \
                    d0 = (v); x0 = (xx); y0 = (yy);                          \
                } else { d1 = (v); x1 = (xx); y1 = (yy); }                   \
            } else { d2v = (v); x2 = (xx); y2 = (yy); }                      \
        } else { d3 = (v); x3 = (xx); y3 = (yy); }                           \
    }

__global__ __launch_bounds__(NTHR) void anchor_knn_kernel(
    const float* __restrict__ nodes,   // (B,2,2)
    const float* __restrict__ ancS,    // (B,M,2)
    const float* __restrict__ ancL,    // (B,M,2)
    const float* __restrict__ W1,      // (64,2)
    const float* __restrict__ b1,      // (64,)
    const float* __restrict__ W2,      // (64,64)
    const float* __restrict__ b2,      // (64,)
    float* __restrict__ out)           // (2,B,64): hs then hl
{
    __shared__ float sW2t[EMB * 65];   // transposed W2, padded
    __shared__ float sh[4 * EMB];      // hidden acts / contrib buffer
    __shared__ float scd[8 * 4];       // per-warp winner distances
    __shared__ float scx[8 * 4];       // per-warp winner x
    __shared__ float scy[8 * 4];       // per-warp winner y
    __shared__ float sta[4 * 2];       // final top-4 coords
    __shared__ float swt[4];           // softmax weights

    const int b    = blockIdx.x;
    const int side = blockIdx.y;
    const int tid  = threadIdx.x;
    const float* __restrict__ anc = side ? ancL : ancS;

    const float gx = nodes[b * 4 + side * 2 + 0];
    const float gy = nodes[b * 4 + side * 2 + 1];

    // Stage W2 transposed into smem
    #pragma unroll
    for (int i = tid; i < EMB * EMB; i += NTHR) {
        int f = i >> 6, e = i & 63;
        sW2t[e * 65 + f] = W2[i];
    }

    // ---- per-thread top-4 with coord payload ----
    float d0 = FINF, d1 = FINF, d2v = FINF, d3 = FINF;
    float x0 = 0.f, y0 = 0.f, x1 = 0.f, y1 = 0.f;
    float x2 = 0.f, y2 = 0.f, x3 = 0.f, y3 = 0.f;

    const float4* __restrict__ a4 =
        reinterpret_cast<const float4*>(anc + (size_t)b * (M_N * 2));

    // 4096 float4s total; each iter handles 2 float4s (4 anchors), 8 iters/thread
    #pragma unroll 4
    for (int i = tid; i < (M_N * 2) / 4; i += 2 * NTHR) {
        float4 va = __ldcs(&a4[i]);          // streaming: no reuse of anchor data
        float4 vb = __ldcs(&a4[i + NTHR]);
        float ax0 = va.x - gx, ay0 = va.y - gy;
        float da = fmaf(ax0, ax0, ay0 * ay0);
        float ax1 = va.z - gx, ay1 = va.w - gy;
        float db = fmaf(ax1, ax1, ay1 * ay1);
        float ax2 = vb.x - gx, ay2 = vb.y - gy;
        float dc = fmaf(ax2, ax2, ay2 * ay2);
        float ax3 = vb.z - gx, ay3 = vb.w - gy;
        float dd = fmaf(ax3, ax3, ay3 * ay3);

        // single cheap test guards the expensive (large, rarely-taken) insert block
        float mgrp = fminf(fminf(da, db), fminf(dc, dd));
        if (mgrp < d3) {
            INSERT3(da, va.x, va.y);
            INSERT3(db, va.z, va.w);
            INSERT3(dc, vb.x, vb.y);
            INSERT3(dd, vb.z, vb.w);
        }
    }

    // ---- warp reduction: merge sorted 4-lists (bitonic lower-half) ----
    const unsigned full = 0xffffffffu;
    #pragma unroll
    for (int off = 16; off > 0; off >>= 1) {
        float e0 = __shfl_down_sync(full, d0,  off);
        float e1 = __shfl_down_sync(full, d1,  off);
        float e2 = __shfl_down_sync(full, d2v, off);
        float e3 = __shfl_down_sync(full, d3,  off);
        float u0 = __shfl_down_sync(full, x0,  off);
        float u1 = __shfl_down_sync(full, x1,  off);
        float u2 = __shfl_down_sync(full, x2,  off);
        float u3 = __shfl_down_sync(full, x3,  off);
        float v0 = __shfl_down_sync(full, y0,  off);
        float v1 = __shfl_down_sync(full, y1,  off);
        float v2 = __shfl_down_sync(full, y2,  off);
        float v3 = __shfl_down_sync(full, y3,  off);
        takemin3(d0,  x0, y0, e3, u3, v3);
        takemin3(d1,  x1, y1, e2, u2, v2);
        takemin3(d2v, x2, y2, e1, u1, v1);
        takemin3(d3,  x3, y3, e0, u0, v0);
        cmpswap3(d0,  x0, y0, d2v, x2, y2);
        cmpswap3(d1,  x1, y1, d3,  x3, y3);
        cmpswap3(d0,  x0, y0, d1,  x1, y1);
        cmpswap3(d2v, x2, y2, d3,  x3, y3);
    }

    const int wid = tid >> 5, lane = tid & 31;
    if (lane == 0) {
        scd[wid * 4 + 0] = d0;  scx[wid * 4 + 0] = x0;  scy[wid * 4 + 0] = y0;
        scd[wid * 4 + 1] = d1;  scx[wid * 4 + 1] = x1;  scy[wid * 4 + 1] = y1;
        scd[wid * 4 + 2] = d2v; scx[wid * 4 + 2] = x2;  scy[wid * 4 + 2] = y2;
        scd[wid * 4 + 3] = d3;  scx[wid * 4 + 3] = x3;  scy[wid * 4 + 3] = y3;
    }
    __syncthreads();

    // ---- final merge + softmax (thread 0, serial) ----
    if (tid == 0) {
        float fd[4] = {FINF, FINF, FINF, FINF};
        float fx[4] = {0, 0, 0, 0}, fy[4] = {0, 0, 0, 0};
        for (int q = 0; q < 32; q++) {
            float v = scd[q];
            if (v < fd[3]) {
                float vx = scx[q], vy = scy[q];
                int p = 3;
                while (p > 0 && v < fd[p - 1]) {
                    fd[p] = fd[p - 1]; fx[p] = fx[p - 1]; fy[p] = fy[p - 1]; p--;
                }
                fd[p] = v; fx[p] = vx; fy[p] = vy;
            }
        }
        // softmax(vals/-tau), vals=-d2 => logits = d2/tau
        const float inv_tau = 1.0f / TAU;
        float mx = fd[3] * inv_tau;
        float e0 = expf(fd[0] * inv_tau - mx);
        float e1 = expf(fd[1] * inv_tau - mx);
        float e2 = expf(fd[2] * inv_tau - mx);
        float e3 = expf(fd[3] * inv_tau - mx);
        float inv_s = 1.0f / (e0 + e1 + e2 + e3);
        swt[0] = e0 * inv_s; swt[1] = e1 * inv_s;
        swt[2] = e2 * inv_s; swt[3] = e3 * inv_s;
        #pragma unroll
        for (int q = 0; q < 4; q++) {
            sta[q * 2 + 0] = fx[q];
            sta[q * 2 + 1] = fy[q];
        }
    }
    __syncthreads();

    // ---- MLP stage A ----
    const int k = tid >> 6, f = tid & 63;
    {
        float ax = sta[k * 2 + 0], ay = sta[k * 2 + 1];
        float hv = fmaf(ax, __ldg(&W1[f * 2 + 0]),
                   fmaf(ay, __ldg(&W1[f * 2 + 1]), __ldg(&b1[f])));
        sh[k * 64 + f] = gelu_exact(hv);
    }
    __syncthreads();

    // ---- MLP stage B ----
    float acc = __ldg(&b2[f]);
    {
        const float* __restrict__ hrow = &sh[k * 64];
        #pragma unroll
        for (int e = 0; e < EMB; e++)
            acc = fmaf(hrow[e], sW2t[e * 65 + f], acc);
    }
    float contrib = gelu_exact(acc) * swt[k];
    __syncthreads();
    sh[tid] = contrib;
    __syncthreads();

    if (tid < 64) {
        float r = sh[tid] + sh[64 + tid] + sh[128 + tid] + sh[192 + tid];
        out[((size_t)side * B_N + b) * 64 + tid] = r;
    }
}

extern "C" void kernel_launch(void* const* d_in, const int* in_sizes, int n_in,
                              void* d_out, int out_size) {
    const float* nodes = (const float*)d_in[0];
    const float* ancS  = (const float*)d_in[1];
    const float* ancL  = (const float*)d_in[2];
    const float* W1    = (const float*)d_in[3];
    const float* b1    = (const float*)d_in[4];
    const float* W2    = (const float*)d_in[5];
    const float* b2    = (const float*)d_in[6];
    float* out = (float*)d_out;

    dim3 grid(B_N, 2);
    anchor_knn_kernel<<<grid, NTHR>>>(nodes, ancS, ancL, W1, b1, W2, b2, out);
}